// round 9
// baseline (speedup 1.0000x reference)
#include <cuda_runtime.h>
#include <cstdint>

using u64 = unsigned long long;

// Problem constants
constexpr int B_ = 16, C_ = 128, H_ = 72, W_ = 200, K_ = 9;
constexpr int CS = H_ * W_;
constexpr size_t BS = (size_t)C_ * CS;
constexpr size_t TOTAL = (size_t)B_ * BS;
constexpr int NCIP = C_ / 2;             // 64 ci-pairs
constexpr int NR = NCIP * K_;            // 576 weight rows (r = cip*9+k)
constexpr int TCO = 16;                  // c_out per CTA

// Scratch: transposed layout + re-laid-out weights (4 directions)
// g_wp2[dir][r][co]: u64 = pack2(w[co][2cip][k], w[co][2cip+1][k]), co 0..127
__device__ float g_tbuf[TOTAL];
__device__ __align__(16) u64 g_wp2[4 * NR * C_];

__device__ __forceinline__ void fma2(u64& d, u64 a, u64 b) {
    asm("fma.rn.f32x2 %0, %1, %2, %0;" : "+l"(d) : "l"(a), "l"(b));
}
__device__ __forceinline__ u64 pack2(float a, float b) {
    u64 r; asm("mov.b64 %0, {%1, %2};" : "=l"(r) : "f"(a), "f"(b)); return r;
}
__device__ __forceinline__ float hsum2(u64 v) {
    float x, y; asm("mov.b64 {%0, %1}, %2;" : "=f"(x), "=f"(y) : "l"(v));
    return x + y;
}
__device__ __forceinline__ void cp_async16(uint32_t saddr, const void* g) {
    asm volatile("cp.async.cg.shared.global [%0], [%1], 16;" :: "r"(saddr), "l"(g));
}
__device__ __forceinline__ void cp_async_wait_all() {
    asm volatile("cp.async.commit_group;\n\tcp.async.wait_group 0;" ::: "memory");
}

__global__ void prep_weights(const float* w0, const float* w1,
                             const float* w2, const float* w3) {
    const float* ws[4] = {w0, w1, w2, w3};
    const int tot = NR * C_;
    for (int i = blockIdx.x * blockDim.x + threadIdx.x; i < 4 * tot;
         i += gridDim.x * blockDim.x) {
        int d = i / tot, rem = i % tot;
        int r = rem / C_, co = rem % C_;
        int cip = r / K_, k = r % K_;
        const float* w = ws[d];
        g_wp2[i] = pack2(w[(size_t)co * C_ * K_ + (2 * cip) * K_ + k],
                         w[(size_t)co * C_ * K_ + (2 * cip + 1) * K_ + k]);
    }
}

// One scan step: cur[b,co,j] += relu( sum_{ci,k} w[co,ci,k] * prev[b,ci,j+k-4] )
// Thread map t = jg*16 + co (co fastest): all smem loads conflict-free.
// Each thread: 1 c_out x JT j. fma2 pairs over (even ci, odd ci).
template <int L, int JT, int NT>
__global__ void __launch_bounds__(NT, 1)
step_kernel(float* __restrict__ base, const u64* __restrict__ wp2,
            int prevIdx, int curIdx) {
    constexpr int QW = L + 8;                    // paired window width (4-halo)
    extern __shared__ __align__(16) u64 sm[];
    u64* w_s = sm;                               // [NR][16 co]
    u64* p_s = sm + NR * TCO;                    // [NCIP][QW]

    const int t = threadIdx.x;
    const int cobase = blockIdx.y * TCO;
    const int b = blockIdx.z;
    float* __restrict__ bb = base + (size_t)b * BS;
    const float* __restrict__ prow = bb + (size_t)prevIdx * L;
    float* __restrict__ crow = bb + (size_t)curIdx * L;

    const int co = t & 15;
    const int jg = t >> 4;
    const int j0 = jg * JT;
    const int gco = cobase + co;

    // ---- stage weights via cp.async 16B (2 co per chunk) ----
    {
        const uint32_t wb = (uint32_t)__cvta_generic_to_shared(w_s);
        #pragma unroll
        for (int i = t; i < NR * 8; i += NT) {
            int r = i >> 3, c = i & 7;
            cp_async16(wb + (uint32_t)i * 16u,
                       wp2 + (size_t)r * C_ + cobase + 2 * c);
        }
    }
    // ---- stage prev row as paired u64 (even ci, odd ci), zero halo ----
    for (int i = t; i < NCIP * QW; i += NT) {
        int cip = i / QW, q = i % QW;
        int gj = q - 4;
        float a = 0.f, c = 0.f;
        if (gj >= 0 && gj < L) {
            a = prow[(size_t)(2 * cip) * CS + gj];
            c = prow[(size_t)(2 * cip + 1) * CS + gj];
        }
        p_s[i] = pack2(a, c);
    }
    // ---- prefetch cur-row base values ----
    float xv[JT];
    #pragma unroll
    for (int n = 0; n < JT; ++n)
        xv[n] = crow[(size_t)gco * CS + j0 + n];

    cp_async_wait_all();
    __syncthreads();

    u64 acc[JT];
    #pragma unroll
    for (int n = 0; n < JT; ++n) acc[n] = 0ull;

    const u64* pw = p_s + j0;
    const u64* wc = w_s + co;

    #pragma unroll 1
    for (int cip = 0; cip < NCIP; ++cip) {
        u64 win[JT + 8];
        #pragma unroll
        for (int q = 0; q < JT + 8; ++q) win[q] = pw[q];
        #pragma unroll
        for (int k = 0; k < K_; ++k) {
            const u64 wk = wc[(size_t)(cip * K_ + k) * TCO];
            #pragma unroll
            for (int n = 0; n < JT; ++n) fma2(acc[n], wk, win[k + n]);
        }
        pw += QW;
    }

    #pragma unroll
    for (int n = 0; n < JT; ++n)
        crow[(size_t)gco * CS + j0 + n] = xv[n] + fmaxf(hsum2(acc[n]), 0.f);
}

// Transpose per (b,c) slab: src slab R x Cc (row-major) -> dst slab Cc x R.
__global__ void transpose_kernel(const float* __restrict__ src, float* __restrict__ dst,
                                 int R, int Cc) {
    __shared__ float tile[32][33];
    const size_t slab = blockIdx.z;
    const float* s = src + slab * (size_t)(R * Cc);
    float* d = dst + slab * (size_t)(R * Cc);
    const int c0 = blockIdx.x * 32;
    const int r0 = blockIdx.y * 32;

    #pragma unroll
    for (int i = 0; i < 32; i += 8) {
        int r = r0 + threadIdx.y + i, c = c0 + threadIdx.x;
        if (r < R && c < Cc) tile[threadIdx.y + i][threadIdx.x] = s[(size_t)r * Cc + c];
    }
    __syncthreads();
    #pragma unroll
    for (int i = 0; i < 32; i += 8) {
        int c = c0 + threadIdx.y + i, r = r0 + threadIdx.x;
        if (r < R && c < Cc) d[(size_t)c * R + r] = tile[threadIdx.x][threadIdx.y + i];
    }
}

// W pass: JT=5, NT=640 (40 jg x 16 co, 20 warps, 5/SMSP)
// H pass: JT=3, NT=384 (24 jg x 16 co, 12 warps, 3/SMSP)
constexpr int SMEM_W = NR * TCO * 8 + NCIP * (W_ + 8) * 8;  // 73,728 + 106,496
constexpr int SMEM_H = NR * TCO * 8 + NCIP * (H_ + 8) * 8;  // 73,728 + 40,960
static_assert(SMEM_W <= 227 * 1024, "smem W over limit");
static_assert(SMEM_H <= 227 * 1024, "smem H over limit");

extern "C" void kernel_launch(void* const* d_in, const int* in_sizes, int n_in,
                              void* d_out, int out_size) {
    const float* x  = (const float*)d_in[0];
    const float* wd = (const float*)d_in[1];
    const float* wu = (const float*)d_in[2];
    const float* wr = (const float*)d_in[3];
    const float* wl = (const float*)d_in[4];
    float* out = (float*)d_out;

    // one-time setup on the (uncaptured) correctness call only
    static float* tbuf = nullptr;
    static u64* wp = nullptr;
    static bool init_done = false;
    if (!init_done) {
        cudaGetSymbolAddress((void**)&tbuf, g_tbuf);
        cudaGetSymbolAddress((void**)&wp, g_wp2);
        cudaFuncSetAttribute((const void*)step_kernel<W_, 5, 640>,
                             cudaFuncAttributeMaxDynamicSharedMemorySize, SMEM_W);
        cudaFuncSetAttribute((const void*)step_kernel<H_, 3, 384>,
                             cudaFuncAttributeMaxDynamicSharedMemorySize, SMEM_H);
        init_done = true;
    }

    // re-lay-out weights (reads inputs every call -> deterministic)
    prep_weights<<<256, 256>>>(wd, wu, wr, wl);

    // working copy of x (scan runs in-place on out)
    cudaMemcpyAsync(out, x, TOTAL * sizeof(float), cudaMemcpyDeviceToDevice);

    const size_t DSTR = (size_t)NR * C_;
    const u64* wpd = wp + 0 * DSTR;
    const u64* wpu = wp + 1 * DSTR;
    const u64* wpr = wp + 2 * DSTR;
    const u64* wpl = wp + 3 * DSTR;

    // ---- down / up: conv along W (contiguous), scan over H ----
    const dim3 gw(1, 8, 16);
    for (int h = 1; h < H_; ++h)
        step_kernel<W_, 5, 640><<<gw, 640, SMEM_W>>>(out, wpd, h - 1, h);
    for (int h = H_ - 2; h >= 0; --h)
        step_kernel<W_, 5, 640><<<gw, 640, SMEM_W>>>(out, wpu, h + 1, h);

    // ---- transpose (B,C,H,W) -> (B,C,W,H) ----
    const dim3 tb(32, 8);
    const dim3 tg1((W_ + 31) / 32, (H_ + 31) / 32, B_ * C_);
    transpose_kernel<<<tg1, tb>>>(out, tbuf, H_, W_);

    // ---- right / left: conv along H (now contiguous), scan over W ----
    const dim3 gh(1, 8, 16);
    for (int w = 1; w < W_; ++w)
        step_kernel<H_, 3, 384><<<gh, 384, SMEM_H>>>(tbuf, wpr, w - 1, w);
    for (int w = W_ - 2; w >= 0; --w)
        step_kernel<H_, 3, 384><<<gh, 384, SMEM_H>>>(tbuf, wpl, w + 1, w);

    // ---- transpose back ----
    const dim3 tg2((H_ + 31) / 32, (W_ + 31) / 32, B_ * C_);
    transpose_kernel<<<tg2, tb>>>(tbuf, out, W_, H_);
}